// round 17
// baseline (speedup 1.0000x reference)
#include <cuda_runtime.h>
#include <cstdint>

// Problem constants (from reference):
//   B=256, P=4096, H=W=512
// Inputs (metadata order):
//   d_in[0]: indices   int32  [B, P, 2]   (JAX x64 disabled: jnp.int64 request -> int32)
//   d_in[1]: num_valid int32  [B]
//   d_in[2]: feats     float32[B, P, 1]
// Output: float32 [B, H, W]
//
// Strategy: compose each output tile in SMEM (zero + shared atomics), then
// stream it to GMEM exactly once with 256-bit stores. No global fill, no
// global atomics -> minimum possible DRAM traffic (268 MB written once).

#define B_  256
#define P_  4096
#define H_  512
#define W_  512
#define HW_ (H_ * W_)

#define THREADS_   1024
#define SPLITS_    8                         // row-groups per batch
#define TROWS_     (H_ / SPLITS_)            // 64 rows per tile
#define TILE_ELEM_ (TROWS_ * W_)             // 32768 floats = 128 KB
#define SMEM_SZ_   (TILE_ELEM_ * 4)
#define PPT_       (P_ / THREADS_)           // 4 points per thread

__device__ __forceinline__ void stg_v8(float* p, const float4& a, const float4& b) {
    asm volatile(
        "st.global.v8.b32 [%0], {%1, %2, %3, %4, %5, %6, %7, %8};"
        :: "l"(p),
           "f"(a.x), "f"(a.y), "f"(a.z), "f"(a.w),
           "f"(b.x), "f"(b.y), "f"(b.z), "f"(b.w)
        : "memory");
}

__global__ __launch_bounds__(THREADS_, 1)
void scatter_densify_smem_kernel(const int* __restrict__ indices,
                                 const int* __restrict__ num_valid,
                                 const float* __restrict__ feats,
                                 float* __restrict__ out)
{
    extern __shared__ float tile[];          // 128 KB: 64 rows x 512 cols

    const int bid = blockIdx.x;
    const int b   = bid >> 3;                // batch (same-batch CTAs adjacent)
    const int g   = bid & (SPLITS_ - 1);     // row group
    const int r0  = g * TROWS_;

    const int nv = __ldg(num_valid + b);

    // ---- Prefetch this batch's points (overlaps SMEM zeroing) ----
    const int2*  ib = reinterpret_cast<const int2*>(indices) + (size_t)b * P_;
    const float* fb = feats + (size_t)b * P_;

    int2  rc[PPT_];
    float fv[PPT_];
    #pragma unroll
    for (int k = 0; k < PPT_; k++) {
        const int p = threadIdx.x + k * THREADS_;
        rc[k] = __ldg(ib + p);               // always in-bounds (P_ allocated)
        fv[k] = __ldg(fb + p);
    }

    // ---- Zero the SMEM tile: 8192 float4 / 1024 threads = 8 iters ----
    float4* t4 = reinterpret_cast<float4*>(tile);
    const float4 z = make_float4(0.f, 0.f, 0.f, 0.f);
    #pragma unroll
    for (int i = threadIdx.x; i < TILE_ELEM_ / 4; i += THREADS_) {
        t4[i] = z;
    }
    __syncthreads();

    // ---- Accumulate points landing in this 64-row window (shared atomics) ----
    #pragma unroll
    for (int k = 0; k < PPT_; k++) {
        const int p = threadIdx.x + k * THREADS_;
        const int r = rc[k].x - r0;          // row relative to tile
        const int c = rc[k].y;
        if (p < nv && (unsigned)r < TROWS_ && (unsigned)c < W_) {
            atomicAdd(&tile[r * W_ + c], fv[k]);
        }
    }
    __syncthreads();

    // ---- Stream the tile to GMEM once: 4096 v8-stores / 1024 thr = 4 iters ----
    float* dst = out + (size_t)b * HW_ + (size_t)r0 * W_;
    #pragma unroll
    for (int i = threadIdx.x; i < TILE_ELEM_ / 8; i += THREADS_) {
        const float4 a = t4[2 * i];
        const float4 c = t4[2 * i + 1];
        stg_v8(dst + 8 * i, a, c);
    }
    // No wait needed: data is in flight from registers; CTA may exit while
    // the store drain proceeds.
}

extern "C" void kernel_launch(void* const* d_in, const int* in_sizes, int n_in,
                              void* d_out, int out_size)
{
    const int*   indices = (const int*)d_in[0];
    const int*   nvalid  = (const int*)d_in[1];
    const float* feats   = (const float*)d_in[2];
    float*       out     = (float*)d_out;

    // 128 KB dynamic SMEM requires an explicit opt-in (host-side attribute,
    // capture-legal; idempotent, called every time for determinism).
    cudaFuncSetAttribute(scatter_densify_smem_kernel,
                         cudaFuncAttributeMaxDynamicSharedMemorySize, SMEM_SZ_);

    scatter_densify_smem_kernel<<<B_ * SPLITS_, THREADS_, SMEM_SZ_>>>(
        indices, nvalid, feats, out);
}